// round 11
// baseline (speedup 1.0000x reference)
#include <cuda_runtime.h>
#include <cstdint>

// Conv1d over W (K=3, pad=1) + roll(+1) on H, as tf32 mma.sync GEMM.
// x: (128,128,28,28) f32, w: (32,128,3) f32 -> out: (128,32,28,28) f32.
//
// Round 11: 8 warps = 4 m16-tiles x 2 k-splits (was 2 m32 x 4 k-splits).
//  - 16 accs/thread -> ~55 regs -> __launch_bounds__(256,4): 4 CTAs/SM (50% occ)
//  - epilogue = one 2-way smem reduce + direct register stores (no gather pass)
//  - B in fragment order in global (48KB), L1-resident: 147.7KB smem leaves 80KB L1
//  - A tile via cp.async.cg; 24-step fully unrolled main loop

typedef unsigned int u32;

__device__ __align__(16) u32 g_wB_frag[2 * 24 * 32 * 8];   // [ks][j][lane][nt*2+r]

__device__ __forceinline__ u32 f2tf32(float v) {
    u32 t;
    asm("cvt.rna.tf32.f32 %0, %1;" : "=r"(t) : "f"(v));
    return t;
}
__device__ __forceinline__ uint32_t smem_u32(const void* p) {
    uint32_t a;
    asm("{ .reg .u64 t; cvta.to.shared.u64 t, %1; cvt.u32.u64 %0, t; }" : "=r"(a) : "l"(p));
    return a;
}
__device__ __forceinline__ void cp16(uint32_t dst, const void* src) {
    asm volatile("cp.async.cg.shared.global [%0], [%1], 16;" :: "r"(dst), "l"(src) : "memory");
}

// wB_frag[((ks*24+j)*32 + lane)*8 + nt*2 + r] = tf32(w[n, ci, kk])
//   n = 8*nt + (lane>>2), k = ks*192 + 8*j + (lane&3) + 4*r, ci = k&127, kk = k>>7
__global__ void wB_kernel(const float* __restrict__ w) {
    int idx = blockIdx.x * 256 + threadIdx.x;   // 12288 total
    if (idx < 12288) {
        int r    = idx & 1;
        int nt   = (idx >> 1) & 3;
        int f    = idx >> 3;
        int lane = f & 31;
        int t    = f >> 5;          // 0..47
        int ks   = t / 24;
        int j    = t % 24;
        int gid  = lane >> 2;
        int tig  = lane & 3;
        int n    = 8 * nt + gid;
        int k    = ks * 192 + 8 * j + tig + 4 * r;
        int ci   = k & 127;
        int kk   = k >> 7;
        g_wB_frag[idx] = f2tf32(w[n * 384 + ci * 3 + kk]);
    }
}

constexpr int RS = 36;                               // A row stride (floats)
constexpr int SMEM_BYTES = 256 * RS * 4 + 64;        // +64B pad for overshoot reads

__global__ __launch_bounds__(256, 4)
void conv_mma_kernel(const float* __restrict__ x, float* __restrict__ out) {
    extern __shared__ __align__(16) u32 smu[];
    const uint32_t sbase = smem_u32(smu);
    const int tid  = threadIdx.x;
    const int b    = blockIdx.y;
    const int h0   = blockIdx.x * 2;

    // ---- async A tile: x[b,ci,h0+hh,4wq..] -> row ci*2+hh, cols 4+4wq (raw f32) ----
    const float* xb = x + (size_t)b * 100352;
#pragma unroll
    for (int t = 0; t < 7; t++) {
        int i  = tid + t * 256;            // 1792 16B copies
        int ci = i / 14;
        int r  = i % 14;
        int hh = r / 7;
        int wq = r % 7;
        cp16(sbase + ((ci * 2 + hh) * RS + 4 + 4 * wq) * 4,
             xb + (size_t)(ci * 28 + h0 + hh) * 28 + 4 * wq);
    }
    asm volatile("cp.async.commit_group;" ::: "memory");

    // halo zeros while copies fly: tile col 3 = x[-1], col 32 = x[28]
    smu[tid * RS + 3]  = 0u;
    smu[tid * RS + 32] = 0u;

    asm volatile("cp.async.wait_group 0;" ::: "memory");
    __syncthreads();

    // ---- main loop: warp = ks*4 + mi ; warp tile = m16 x n32, K = 192 ----
    const int warp = tid >> 5;
    const int lane = tid & 31;
    const int mi   = warp & 3;        // m16 tile: m = 16*mi + gid + 8*q2
    const int ks   = warp >> 2;       // k-split 0..1 (192 k each = 24 k8-steps)
    const int gid  = lane >> 2;
    const int tig  = lane & 3;
    const int hh   = mi >> 1;         // h row within block
    const int mw0  = (mi & 1) * 16;   // w offset of this m16 tile

    float c[4][4];
#pragma unroll
    for (int nt = 0; nt < 4; nt++)
#pragma unroll
        for (int q = 0; q < 4; q++) c[nt][q] = 0.f;

    const u32* As = smu;
    const uint4* Bf = (const uint4*)g_wB_frag + ((size_t)(ks * 24) * 32 + lane) * 2;

#pragma unroll
    for (int j = 0; j < 24; j++) {
        int k0  = ks * 192 + j * 8;
        int kk  = k0 >> 7;
        int ci0 = k0 & 127;
        // A[m][k] at row ci*2+hh, col mw0+gid+kk+3 ; ci = ci0+tig(+4)
        const u32* p = As + (ci0 + tig) * (2 * RS) + hh * RS + mw0 + gid + kk + 3;

        uint4 b0 = Bf[j * 64 + 0];     // {nt0r0, nt0r1, nt1r0, nt1r1}
        uint4 b1 = Bf[j * 64 + 1];     // {nt2r0, nt2r1, nt3r0, nt3r1}

        u32 a0 = p[0];
        u32 a1 = p[8];
        u32 a2 = p[4 * 2 * RS];        // tig+4 -> ci+4
        u32 a3 = p[4 * 2 * RS + 8];

        u32 bb[4][2] = { {b0.x, b0.y}, {b0.z, b0.w}, {b1.x, b1.y}, {b1.z, b1.w} };
#pragma unroll
        for (int nt = 0; nt < 4; nt++) {
            asm volatile(
                "mma.sync.aligned.m16n8k8.row.col.f32.tf32.tf32.f32 "
                "{%0,%1,%2,%3}, {%4,%5,%6,%7}, {%8,%9}, {%0,%1,%2,%3};"
                : "+f"(c[nt][0]), "+f"(c[nt][1]), "+f"(c[nt][2]), "+f"(c[nt][3])
                : "r"(a0), "r"(a1), "r"(a2), "r"(a3),
                  "r"(bb[nt][0]), "r"(bb[nt][1]));
        }
    }

    // ---- 2-way k-split reduce + direct store ----
    __syncthreads();                   // A tile dead; reuse as partial buffer
    float* red = (float*)smu;          // [mi][16][32] = 2048 floats
    if (ks == 1) {
        float* dst = red + mi * 512;
#pragma unroll
        for (int i = 0; i < 16; i++)
            dst[i * 32 + lane] = c[i >> 2][i & 3];
    }
    __syncthreads();

    if (ks == 0) {
        const float* src = red + mi * 512;
#pragma unroll
        for (int i = 0; i < 16; i++)
            c[i >> 2][i & 3] += src[i * 32 + lane];

        const int hp = (h0 + hh + 1) % 28;   // roll(+1) along H
        float* ob = out + (size_t)b * 25088 + hp * 28;
#pragma unroll
        for (int nt = 0; nt < 4; nt++)
#pragma unroll
            for (int q = 0; q < 4; q++) {
                int mw = mw0 + gid + 8 * (q >> 1);
                int co = 8 * nt + 2 * tig + (q & 1);
                if (mw < 28)
                    ob[(size_t)co * 784 + mw] = c[nt][q];
            }
    }
}

extern "C" void kernel_launch(void* const* d_in, const int* in_sizes, int n_in,
                              void* d_out, int out_size) {
    const float* x = (const float*)d_in[0];
    const float* w = (const float*)d_in[1];
    float* out = (float*)d_out;

    cudaFuncSetAttribute(conv_mma_kernel,
                         cudaFuncAttributeMaxDynamicSharedMemorySize, SMEM_BYTES);

    wB_kernel<<<48, 256>>>(w);
    conv_mma_kernel<<<dim3(14, 128), 256, SMEM_BYTES>>>(x, out);
}

// round 12
// speedup vs baseline: 1.1032x; 1.1032x over previous
#include <cuda_runtime.h>
#include <cstdint>

// Conv1d over W (K=3, pad=1) + roll(+1) on H, as tf32 mma.sync GEMM.
// x: (128,128,28,28) f32, w: (32,128,3) f32 -> out: (128,32,28,28) f32.
//
// Round 12 = round 10 structure (2 m32-tiles x 4 k-splits: the minimum-B-
// traffic warp decomposition at <=32 accs) forced to 4 CTAs/SM.
// Live regs ~58 (32 acc + 8 A + 8 B + addressing, loop fully unrolled);
// round 10's regs=80 was just ptxas slack under the occ-3 cap.
//  - B precomputed in mma fragment order in global (48KB, L1-resident)
//  - A tile via cp.async.cg (36.9KB smem); all-warp gather epilogue

typedef unsigned int u32;

__device__ __align__(16) u32 g_wB_frag[4 * 12 * 32 * 8];   // [ks][j][lane][nt*2+r]

__device__ __forceinline__ u32 f2tf32(float v) {
    u32 t;
    asm("cvt.rna.tf32.f32 %0, %1;" : "=r"(t) : "f"(v));
    return t;
}
__device__ __forceinline__ uint32_t smem_u32(const void* p) {
    uint32_t a;
    asm("{ .reg .u64 t; cvta.to.shared.u64 t, %1; cvt.u32.u64 %0, t; }" : "=r"(a) : "l"(p));
    return a;
}
__device__ __forceinline__ void cp16(uint32_t dst, const void* src) {
    asm volatile("cp.async.cg.shared.global [%0], [%1], 16;" :: "r"(dst), "l"(src) : "memory");
}

// wB_frag[((ks*12+j)*32 + lane)*8 + nt*2 + r] = tf32(w[n, ci, kk])
//   n = 8*nt + (lane>>2), k = ks*96 + 8*j + (lane&3) + 4*r, ci = k&127, kk = k>>7
__global__ void wB_kernel(const float* __restrict__ w) {
    int idx = blockIdx.x * 256 + threadIdx.x;   // 12288 total
    if (idx < 12288) {
        int r    = idx & 1;
        int nt   = (idx >> 1) & 3;
        int f    = idx >> 3;
        int lane = f & 31;
        int t    = f >> 5;
        int ks   = t / 12;
        int j    = t % 12;
        int gid  = lane >> 2;
        int tig  = lane & 3;
        int n    = 8 * nt + gid;
        int k    = ks * 96 + 8 * j + tig + 4 * r;
        int ci   = k & 127;
        int kk   = k >> 7;
        g_wB_frag[idx] = f2tf32(w[n * 384 + ci * 3 + kk]);
    }
}

constexpr int RS = 36;                               // A row stride (floats)
constexpr int SMEM_BYTES = 256 * RS * 4 + 64;        // +64B pad for overshoot reads

__global__ __launch_bounds__(256, 4)
void conv_mma_kernel(const float* __restrict__ x, float* __restrict__ out) {
    extern __shared__ __align__(16) u32 smu[];
    const uint32_t sbase = smem_u32(smu);
    const int tid  = threadIdx.x;
    const int b    = blockIdx.y;
    const int h0   = blockIdx.x * 2;

    // ---- async A tile: x[b,ci,h0+hh,4wq..] -> row ci*2+hh, cols 4+4wq (raw f32) ----
    const float* xb = x + (size_t)b * 100352;
#pragma unroll
    for (int t = 0; t < 7; t++) {
        int i  = tid + t * 256;            // 1792 16B copies
        int ci = i / 14;
        int r  = i % 14;
        int hh = r / 7;
        int wq = r % 7;
        cp16(sbase + ((ci * 2 + hh) * RS + 4 + 4 * wq) * 4,
             xb + (size_t)(ci * 28 + h0 + hh) * 28 + 4 * wq);
    }
    asm volatile("cp.async.commit_group;" ::: "memory");

    // halo zeros while copies fly: tile col 3 = x[-1], col 32 = x[28]
    smu[tid * RS + 3]  = 0u;
    smu[tid * RS + 32] = 0u;

    asm volatile("cp.async.wait_group 0;" ::: "memory");
    __syncthreads();

    // ---- main loop: 8 warps = 2 m32-tiles x 4 k-splits (96 k each) ----
    const int warp = tid >> 5;
    const int lane = tid & 31;
    const int mi   = warp & 1;        // m32 tile == hh
    const int ks   = warp >> 1;       // k-split 0..3 (12 k8-steps each)
    const int gid  = lane >> 2;
    const int tig  = lane & 3;

    float c[2][4][4];
#pragma unroll
    for (int mt = 0; mt < 2; mt++)
#pragma unroll
        for (int nt = 0; nt < 4; nt++)
#pragma unroll
            for (int q = 0; q < 4; q++) c[mt][nt][q] = 0.f;

    const u32* As = smu;
    const uint4* Bf = (const uint4*)g_wB_frag + ((size_t)(ks * 12) * 32 + lane) * 2;

#pragma unroll
    for (int j = 0; j < 12; j++) {
        int k0  = ks * 96 + j * 8;
        int kk  = k0 >> 7;
        int ci0 = k0 & 127;
        // A[m][k] at (ci*2+hh)*RS + mw + kk + 3 ; ci = ci0+tig(+4), mw = mt*16+gid(+8)
        const u32* ap = As + (ci0 + tig) * (2 * RS) + mi * RS + gid + kk + 3;

        // B fragments: 2 coalesced LDG.128 (L1-resident after first block on SM)
        uint4 b0 = Bf[j * 64 + 0];     // {nt0r0, nt0r1, nt1r0, nt1r1}
        uint4 b1 = Bf[j * 64 + 1];     // {nt2r0, nt2r1, nt3r0, nt3r1}

        u32 a[2][4];
#pragma unroll
        for (int mt = 0; mt < 2; mt++) {
            const u32* p = ap + mt * 16;
            a[mt][0] = p[0];
            a[mt][1] = p[8];
            a[mt][2] = p[4 * 2 * RS];        // tig+4 -> ci+4
            a[mt][3] = p[4 * 2 * RS + 8];
        }

        u32 bb[4][2] = { {b0.x, b0.y}, {b0.z, b0.w}, {b1.x, b1.y}, {b1.z, b1.w} };
#pragma unroll
        for (int mt = 0; mt < 2; mt++)
#pragma unroll
            for (int nt = 0; nt < 4; nt++) {
                asm volatile(
                    "mma.sync.aligned.m16n8k8.row.col.f32.tf32.tf32.f32 "
                    "{%0,%1,%2,%3}, {%4,%5,%6,%7}, {%8,%9}, {%0,%1,%2,%3};"
                    : "+f"(c[mt][nt][0]), "+f"(c[mt][nt][1]),
                      "+f"(c[mt][nt][2]), "+f"(c[mt][nt][3])
                    : "r"(a[mt][0]), "r"(a[mt][1]), "r"(a[mt][2]), "r"(a[mt][3]),
                      "r"(bb[nt][0]), "r"(bb[nt][1]));
            }
    }

    // ---- all warps dump partials: region (ks*2+mi), layout i*33 + lane ----
    __syncthreads();
    float* red = (float*)smu;   // 8*1056 floats = 33792 B, fits in A region
    {
        float* dst = red + (ks * 2 + mi) * 1056;
#pragma unroll
        for (int i = 0; i < 32; i++)
            dst[i * 33 + lane] = c[i >> 4][(i >> 2) & 3][i & 3];
    }
    __syncthreads();

    // ---- 256-thread gather: sum 4 k-splits, store with roll(+1) on H ----
    float* ob = out + (size_t)b * 25088;
#pragma unroll
    for (int t = 0; t < 7; t++) {
        int idx = t * 256 + tid;           // 1792 outputs: (emi, co, mw)
        int emi = idx / 896;
        int r2  = idx % 896;
        int co  = r2 / 28;
        int mw  = r2 % 28;
        // invert the mma fragment map
        int mt  = mw >> 4;
        int rr  = mw & 15;
        int q2  = rr >> 3;
        int g2  = rr & 7;
        int nt  = co >> 3;
        int tg  = (co & 7) >> 1;
        int q1  = co & 1;
        int ln  = g2 * 4 + tg;
        int fi  = mt * 16 + nt * 4 + q2 * 2 + q1;
        int off = fi * 33 + ln + emi * 1056;
        float v = red[off] + red[off + 2112] + red[off + 4224] + red[off + 6336];
        int hp  = (h0 + emi + 1) % 28;     // roll(+1) along H
        ob[(size_t)co * 784 + hp * 28 + mw] = v;
    }
}

extern "C" void kernel_launch(void* const* d_in, const int* in_sizes, int n_in,
                              void* d_out, int out_size) {
    const float* x = (const float*)d_in[0];
    const float* w = (const float*)d_in[1];
    float* out = (float*)d_out;

    cudaFuncSetAttribute(conv_mma_kernel,
                         cudaFuncAttributeMaxDynamicSharedMemorySize, SMEM_BYTES);

    wB_kernel<<<48, 256>>>(w);
    conv_mma_kernel<<<dim3(14, 128), 256, SMEM_BYTES>>>(x, out);
}

// round 13
// speedup vs baseline: 1.2049x; 1.0922x over previous
#include <cuda_runtime.h>
#include <cstdint>

// Conv1d over W (K=3, pad=1) + roll(+1) on H, as tf32 mma.sync GEMM.
// x: (128,128,28,28) f32, w: (32,128,3) f32 -> out: (128,32,28,28) f32.
//
// Round 13 = round 12 + SoA B-fragment layout. The old [lane][8 u32] AoS
// gave 32B lane stride -> each LDG.128 touched 8 cache lines (8 L1
// wavefronts); B was 1536 of ~2300 wavefronts per block. Split into two
// arrays (b0: nt0/nt1, b1: nt2/nt3), each [ks][j][lane] uint4 -> 16B lane
// stride, fully coalesced 4-wavefront loads. B L1 traffic halves.
//  - 8 warps = 2 m32-tiles x 4 k-splits, 4 CTAs/SM, regs 64
//  - A tile via cp.async.cg (36.9KB smem); all-warp gather epilogue

typedef unsigned int u32;

__device__ __align__(16) uint4 g_wB0[4 * 12 * 32];   // [ks][j][lane] = {nt0r0,nt0r1,nt1r0,nt1r1}
__device__ __align__(16) uint4 g_wB1[4 * 12 * 32];   // [ks][j][lane] = {nt2r0,nt2r1,nt3r0,nt3r1}

__device__ __forceinline__ u32 f2tf32(float v) {
    u32 t;
    asm("cvt.rna.tf32.f32 %0, %1;" : "=r"(t) : "f"(v));
    return t;
}
__device__ __forceinline__ uint32_t smem_u32(const void* p) {
    uint32_t a;
    asm("{ .reg .u64 t; cvta.to.shared.u64 t, %1; cvt.u32.u64 %0, t; }" : "=r"(a) : "l"(p));
    return a;
}
__device__ __forceinline__ void cp16(uint32_t dst, const void* src) {
    asm volatile("cp.async.cg.shared.global [%0], [%1], 16;" :: "r"(dst), "l"(src) : "memory");
}

// element (arr, ks, j, lane, e): nt = arr*2 + (e>>1), r = e&1
//   n = 8*nt + (lane>>2), k = ks*96 + 8*j + (lane&3) + 4*r, ci = k&127, kk = k>>7
__global__ void wB_kernel(const float* __restrict__ w) {
    int idx = blockIdx.x * 256 + threadIdx.x;   // 12288 total
    if (idx < 12288) {
        int arr  = idx / 6144;
        int rem  = idx % 6144;
        int e    = rem & 3;
        int lane = (rem >> 2) & 31;
        int t    = rem >> 7;        // 0..47
        int ks   = t / 12;
        int j    = t % 12;
        int nt   = arr * 2 + (e >> 1);
        int r    = e & 1;
        int n    = 8 * nt + (lane >> 2);
        int k    = ks * 96 + 8 * j + (lane & 3) + 4 * r;
        int ci   = k & 127;
        int kk   = k >> 7;
        u32* dst = (u32*)(arr ? g_wB1 : g_wB0);
        dst[(t * 32 + lane) * 4 + e] = f2tf32(w[n * 384 + ci * 3 + kk]);
    }
}

constexpr int RS = 36;                               // A row stride (floats)
constexpr int SMEM_BYTES = 256 * RS * 4 + 64;        // +64B pad for overshoot reads

__global__ __launch_bounds__(256, 4)
void conv_mma_kernel(const float* __restrict__ x, float* __restrict__ out) {
    extern __shared__ __align__(16) u32 smu[];
    const uint32_t sbase = smem_u32(smu);
    const int tid  = threadIdx.x;
    const int b    = blockIdx.y;
    const int h0   = blockIdx.x * 2;

    // ---- async A tile: x[b,ci,h0+hh,4wq..] -> row ci*2+hh, cols 4+4wq (raw f32) ----
    const float* xb = x + (size_t)b * 100352;
#pragma unroll
    for (int t = 0; t < 7; t++) {
        int i  = tid + t * 256;            // 1792 16B copies
        int ci = i / 14;
        int r  = i % 14;
        int hh = r / 7;
        int wq = r % 7;
        cp16(sbase + ((ci * 2 + hh) * RS + 4 + 4 * wq) * 4,
             xb + (size_t)(ci * 28 + h0 + hh) * 28 + 4 * wq);
    }
    asm volatile("cp.async.commit_group;" ::: "memory");

    // halo zeros while copies fly: tile col 3 = x[-1], col 32 = x[28]
    smu[tid * RS + 3]  = 0u;
    smu[tid * RS + 32] = 0u;

    asm volatile("cp.async.wait_group 0;" ::: "memory");
    __syncthreads();

    // ---- main loop: 8 warps = 2 m32-tiles x 4 k-splits (96 k each) ----
    const int warp = tid >> 5;
    const int lane = tid & 31;
    const int mi   = warp & 1;        // m32 tile == hh
    const int ks   = warp >> 1;       // k-split 0..3 (12 k8-steps each)
    const int gid  = lane >> 2;
    const int tig  = lane & 3;

    float c[2][4][4];
#pragma unroll
    for (int mt = 0; mt < 2; mt++)
#pragma unroll
        for (int nt = 0; nt < 4; nt++)
#pragma unroll
            for (int q = 0; q < 4; q++) c[mt][nt][q] = 0.f;

    const u32* As = smu;
    const uint4* B0 = g_wB0 + (ks * 12) * 32 + lane;   // lane stride 16B: coalesced
    const uint4* B1 = g_wB1 + (ks * 12) * 32 + lane;

#pragma unroll
    for (int j = 0; j < 12; j++) {
        int k0  = ks * 96 + j * 8;
        int kk  = k0 >> 7;
        int ci0 = k0 & 127;
        // A[m][k] at (ci*2+hh)*RS + mw + kk + 3 ; ci = ci0+tig(+4), mw = mt*16+gid(+8)
        const u32* ap = As + (ci0 + tig) * (2 * RS) + mi * RS + gid + kk + 3;

        uint4 b0 = B0[j * 32];         // {nt0r0, nt0r1, nt1r0, nt1r1}
        uint4 b1 = B1[j * 32];         // {nt2r0, nt2r1, nt3r0, nt3r1}

        u32 a[2][4];
#pragma unroll
        for (int mt = 0; mt < 2; mt++) {
            const u32* p = ap + mt * 16;
            a[mt][0] = p[0];
            a[mt][1] = p[8];
            a[mt][2] = p[4 * 2 * RS];        // tig+4 -> ci+4
            a[mt][3] = p[4 * 2 * RS + 8];
        }

        u32 bb[4][2] = { {b0.x, b0.y}, {b0.z, b0.w}, {b1.x, b1.y}, {b1.z, b1.w} };
#pragma unroll
        for (int mt = 0; mt < 2; mt++)
#pragma unroll
            for (int nt = 0; nt < 4; nt++) {
                asm volatile(
                    "mma.sync.aligned.m16n8k8.row.col.f32.tf32.tf32.f32 "
                    "{%0,%1,%2,%3}, {%4,%5,%6,%7}, {%8,%9}, {%0,%1,%2,%3};"
                    : "+f"(c[mt][nt][0]), "+f"(c[mt][nt][1]),
                      "+f"(c[mt][nt][2]), "+f"(c[mt][nt][3])
                    : "r"(a[mt][0]), "r"(a[mt][1]), "r"(a[mt][2]), "r"(a[mt][3]),
                      "r"(bb[nt][0]), "r"(bb[nt][1]));
            }
    }

    // ---- all warps dump partials: region (ks*2+mi), layout i*33 + lane ----
    __syncthreads();
    float* red = (float*)smu;   // 8*1056 floats = 33792 B, fits in A region
    {
        float* dst = red + (ks * 2 + mi) * 1056;
#pragma unroll
        for (int i = 0; i < 32; i++)
            dst[i * 33 + lane] = c[i >> 4][(i >> 2) & 3][i & 3];
    }
    __syncthreads();

    // ---- 256-thread gather: sum 4 k-splits, store with roll(+1) on H ----
    float* ob = out + (size_t)b * 25088;
#pragma unroll
    for (int t = 0; t < 7; t++) {
        int idx = t * 256 + tid;           // 1792 outputs: (emi, co, mw)
        int emi = idx / 896;
        int r2  = idx % 896;
        int co  = r2 / 28;
        int mw  = r2 % 28;
        // invert the mma fragment map
        int mt  = mw >> 4;
        int rr  = mw & 15;
        int q2  = rr >> 3;
        int g2  = rr & 7;
        int nt  = co >> 3;
        int tg  = (co & 7) >> 1;
        int q1  = co & 1;
        int ln  = g2 * 4 + tg;
        int fi  = mt * 16 + nt * 4 + q2 * 2 + q1;
        int off = fi * 33 + ln + emi * 1056;
        float v = red[off] + red[off + 2112] + red[off + 4224] + red[off + 6336];
        int hp  = (h0 + emi + 1) % 28;     // roll(+1) along H
        ob[(size_t)co * 784 + hp * 28 + mw] = v;
    }
}

extern "C" void kernel_launch(void* const* d_in, const int* in_sizes, int n_in,
                              void* d_out, int out_size) {
    const float* x = (const float*)d_in[0];
    const float* w = (const float*)d_in[1];
    float* out = (float*)d_out;

    cudaFuncSetAttribute(conv_mma_kernel,
                         cudaFuncAttributeMaxDynamicSharedMemorySize, SMEM_BYTES);

    wB_kernel<<<48, 256>>>(w);
    conv_mma_kernel<<<dim3(14, 128), 256, SMEM_BYTES>>>(x, out);
}